// round 11
// baseline (speedup 1.0000x reference)
#include <cuda_runtime.h>
#include <cuda_bf16.h>
#include <cstdint>

#define D        128
#define N1       81920
#define BATCH    8192
#define KNB      10
#define NTHREADS 256
#define KPAD     136        // padded k-stride in bf16 elems
#define ROWB     (KPAD * 2) // 272 bytes per row

// ---------------- device-global scratch (allocation-free rule) ----------------
__device__ float g_h1[(size_t)N1 * D];                 // layer-1 embeddings

// ---------------- PTX helpers ----------------
__device__ __forceinline__ uint32_t smem_u32(const void* p) {
    uint32_t a;
    asm("{ .reg .u64 t; cvta.to.shared.u64 t, %1; cvt.u32.u64 %0, t; }"
        : "=r"(a) : "l"(p));
    return a;
}
#define LDSM4(r, addr)                                                       \
    asm volatile("ldmatrix.sync.aligned.m8n8.x4.shared.b16 {%0,%1,%2,%3}, [%4];" \
                 : "=r"((r)[0]), "=r"((r)[1]), "=r"((r)[2]), "=r"((r)[3])    \
                 : "r"(addr))
#define MMA16816(c, a, b0, b1)                                               \
    asm volatile("mma.sync.aligned.m16n8k16.row.col.f32.bf16.bf16.f32 "      \
                 "{%0,%1,%2,%3}, {%4,%5,%6,%7}, {%8,%9}, {%0,%1,%2,%3};"     \
                 : "+f"((c)[0]), "+f"((c)[1]), "+f"((c)[2]), "+f"((c)[3])    \
                 : "r"((a)[0]), "r"((a)[1]), "r"((a)[2]), "r"((a)[3]),       \
                   "r"(b0), "r"(b1))

__device__ __forceinline__ uint32_t pack_bf2(float a, float b) {
    __nv_bfloat16 ha = __float2bfloat16_rn(a), hb = __float2bfloat16_rn(b);
    return (uint32_t)__bfloat16_as_ushort(ha) |
           ((uint32_t)__bfloat16_as_ushort(hb) << 16);
}
// split float4 into bf16 hi + bf16 residual lo; 8-B store each
__device__ __forceinline__ void split_store(char* hi_p, char* lo_p, float4 v) {
    __nv_bfloat16 hx = __float2bfloat16_rn(v.x), hy = __float2bfloat16_rn(v.y);
    __nv_bfloat16 hz = __float2bfloat16_rn(v.z), hw = __float2bfloat16_rn(v.w);
    uint2 hv, lv;
    hv.x = (uint32_t)__bfloat16_as_ushort(hx) | ((uint32_t)__bfloat16_as_ushort(hy) << 16);
    hv.y = (uint32_t)__bfloat16_as_ushort(hz) | ((uint32_t)__bfloat16_as_ushort(hw) << 16);
    lv.x = pack_bf2(v.x - __bfloat162float(hx), v.y - __bfloat162float(hy));
    lv.y = pack_bf2(v.z - __bfloat162float(hz), v.w - __bfloat162float(hw));
    *(uint2*)hi_p = hv;
    *(uint2*)lo_p = lv;
}

// one K=128 phase of the split GEMM: acc += Ah*Bh + Al*Bh + Ah*Bl
// NQ = number of 16-col groups in this warp's N tile
template <int NQ>
__device__ __forceinline__ void mma_phase(uint32_t aH, uint32_t aL,
                                          uint32_t bH, uint32_t bL,
                                          int lane, float acc[2][2 * NQ][4]) {
    const uint32_t pa = (uint32_t)((lane & 15) * ROWB + (lane >> 4) * 16);
    const uint32_t pb = (uint32_t)(((lane & 7) + ((lane >> 4) << 3)) * ROWB +
                                   ((lane >> 3) & 1) * 16);
    #pragma unroll
    for (int ks = 0; ks < 8; ks++) {
        const uint32_t ko = ks * 32;
        uint32_t ah[2][4], al[2][4];
        #pragma unroll
        for (int mt = 0; mt < 2; mt++) {
            LDSM4(ah[mt], aH + pa + mt * 16 * ROWB + ko);
            LDSM4(al[mt], aL + pa + mt * 16 * ROWB + ko);
        }
        #pragma unroll
        for (int nq = 0; nq < NQ; nq++) {
            uint32_t bh[4], bl[4];
            LDSM4(bh, bH + pb + nq * 16 * ROWB + ko);
            LDSM4(bl, bL + pb + nq * 16 * ROWB + ko);
            #pragma unroll
            for (int mt = 0; mt < 2; mt++) {
                MMA16816(acc[mt][nq * 2 + 0], ah[mt], bh[0], bh[1]);
                MMA16816(acc[mt][nq * 2 + 1], ah[mt], bh[2], bh[3]);
                MMA16816(acc[mt][nq * 2 + 0], al[mt], bh[0], bh[1]);
                MMA16816(acc[mt][nq * 2 + 1], al[mt], bh[2], bh[3]);
                MMA16816(acc[mt][nq * 2 + 0], ah[mt], bl[0], bl[1]);
                MMA16816(acc[mt][nq * 2 + 1], ah[mt], bl[2], bl[3]);
            }
        }
    }
}

// ---------------- fused SAGE layer -------------------------------------------
// TM_ rows per block. Warp grid: WM_ x WN_ (=8 warps), warp tile 32 x (128/WN_).
template <int LAYER, int TM_, int WM_, int WN_>
__global__ __launch_bounds__(NTHREADS, 1)
void sage_mma_kernel(const float* __restrict__ feats_in,
                     const float* __restrict__ Wg,
                     const int*   __restrict__ self_idx,
                     const int*   __restrict__ neigh_idx,
                     float*       __restrict__ out_ext) {
    constexpr int NW  = 128 / WN_;          // cols per warp tile
    constexpr int NQ  = NW / 16;
    constexpr int RPW = TM_ / 8;            // gather rows per warp
    constexpr int ATILE = TM_ * ROWB;
    constexpr int OFF_A0H = 0;
    constexpr int OFF_A0L = ATILE;
    constexpr int OFF_A1H = 2 * ATILE;
    constexpr int OFF_A1L = 3 * ATILE;
    constexpr int OFF_BH  = 4 * ATILE;
    constexpr int OFF_BL  = 4 * ATILE + 128 * ROWB;

    extern __shared__ char smem[];
    const uint32_t sb = smem_u32(smem);
    const int t = threadIdx.x, lane = t & 31, wid = t >> 5;

    const float* feats = (LAYER == 1) ? feats_in : g_h1;
    float*       out   = (LAYER == 1) ? g_h1 : out_ext;

    // ---- stage B phase 0: coalesced read of W[:, 0:128], split hi/lo ----
    {
        const int j = wid + 0 * 8;          // warp w covers rows w, w+8, ...
        #pragma unroll
        for (int it = 0; it < 16; it++) {
            const int row = wid + it * 8;
            float4 v = __ldg((const float4*)(Wg + row * 256) + lane);
            split_store(smem + OFF_BH + row * ROWB + lane * 8,
                        smem + OFF_BL + row * ROWB + lane * 8, v);
        }
        (void)j;
    }

    // ---- gather: RPW rows/warp, 4 rows pipelined (44 loads in flight) ----
    {
        #pragma unroll
        for (int base = 0; base < RPW; base += 4) {
            int   rows[4], nsel[4], nn[4][KNB];
            #pragma unroll
            for (int jj = 0; jj < 4; jj++) {
                rows[jj] = blockIdx.x * TM_ + wid * RPW + base + jj;
                nsel[jj] = __ldg(&self_idx[rows[jj]]);
                #pragma unroll
                for (int k = 0; k < KNB; k++)
                    nn[jj][k] = __ldg(&neigh_idx[rows[jj] * KNB + k]);
            }
            float4 s[4], a[4];
            #pragma unroll
            for (int jj = 0; jj < 4; jj++) {
                s[jj] = __ldg((const float4*)&feats[(size_t)nsel[jj] * D] + lane);
                a[jj] = make_float4(0.f, 0.f, 0.f, 0.f);
            }
            #pragma unroll
            for (int k = 0; k < KNB; k++)
                #pragma unroll
                for (int jj = 0; jj < 4; jj++) {
                    float4 f = __ldg((const float4*)&feats[(size_t)nn[jj][k] * D] + lane);
                    a[jj].x += f.x; a[jj].y += f.y; a[jj].z += f.z; a[jj].w += f.w;
                }
            const float inv = 1.0f / (float)KNB;
            #pragma unroll
            for (int jj = 0; jj < 4; jj++) {
                a[jj].x *= inv; a[jj].y *= inv; a[jj].z *= inv; a[jj].w *= inv;
                const int r  = wid * RPW + base + jj;
                const int so = r * ROWB + lane * 8;
                split_store(smem + OFF_A0H + so, smem + OFF_A0L + so, s[jj]);
                split_store(smem + OFF_A1H + so, smem + OFF_A1L + so, a[jj]);
            }
        }
    }
    __syncthreads();

    // ---- warp tiling ----
    const int wm = wid % WM_, wn = wid / WM_;
    const uint32_t aoff = (uint32_t)(wm * 32 * ROWB);
    const uint32_t boff = (uint32_t)(wn * NW * ROWB);

    float acc[2][2 * NQ][4];
    #pragma unroll
    for (int mt = 0; mt < 2; mt++)
        #pragma unroll
        for (int nt = 0; nt < 2 * NQ; nt++)
            #pragma unroll
            for (int c = 0; c < 4; c++) acc[mt][nt][c] = 0.0f;

    // ---- phase 0: self features x W[:, 0:128] ----
    mma_phase<NQ>(sb + OFF_A0H + aoff, sb + OFF_A0L + aoff,
                  sb + OFF_BH + boff,  sb + OFF_BL + boff, lane, acc);

    // ---- restage B for phase 1 ----
    __syncthreads();
    {
        #pragma unroll
        for (int it = 0; it < 16; it++) {
            const int row = wid + it * 8;
            float4 v = __ldg((const float4*)(Wg + row * 256 + 128) + lane);
            split_store(smem + OFF_BH + row * ROWB + lane * 8,
                        smem + OFF_BL + row * ROWB + lane * 8, v);
        }
    }
    __syncthreads();

    // ---- phase 1: agg features x W[:, 128:256] ----
    mma_phase<NQ>(sb + OFF_A1H + aoff, sb + OFF_A1L + aoff,
                  sb + OFF_BH + boff,  sb + OFF_BL + boff, lane, acc);

    // ---- epilogue: ReLU + float2 stores ----
    const int rb = blockIdx.x * TM_ + wm * 32 + (lane >> 2);
    const int cb = wn * NW + (lane & 3) * 2;
    #pragma unroll
    for (int mt = 0; mt < 2; mt++)
        #pragma unroll
        for (int nt = 0; nt < 2 * NQ; nt++) {
            const int row = rb + mt * 16;
            const int col = cb + nt * 8;
            float2 v0 = make_float2(fmaxf(acc[mt][nt][0], 0.f),
                                    fmaxf(acc[mt][nt][1], 0.f));
            float2 v1 = make_float2(fmaxf(acc[mt][nt][2], 0.f),
                                    fmaxf(acc[mt][nt][3], 0.f));
            *(float2*)&out[(size_t)row * D + col]       = v0;
            *(float2*)&out[(size_t)(row + 8) * D + col] = v1;
        }
}

// ---------------- launch ----------------
extern "C" void kernel_launch(void* const* d_in, const int* in_sizes, int n_in,
                              void* d_out, int out_size) {
    const float* raw_features = (const float*)d_in[0];
    const float* W1           = (const float*)d_in[1];
    const float* W2           = (const float*)d_in[2];
    const int*   layer1_nodes = (const int*)d_in[3];
    const int*   neigh0_idx   = (const int*)d_in[4];
    const int*   map_batch    = (const int*)d_in[5];
    const int*   neigh1_idx   = (const int*)d_in[6];
    float*       out          = (float*)d_out;

    // layer 1: TM=128, warps 4m x 2n (tile 32x64)
    constexpr int SMEM1 = 4 * 128 * ROWB + 2 * 128 * ROWB;   // 208896
    // layer 2: TM=64,  warps 2m x 4n (tile 32x32)
    constexpr int SMEM2 = 4 * 64 * ROWB + 2 * 128 * ROWB;    // 139264

    cudaFuncSetAttribute((const void*)sage_mma_kernel<1, 128, 4, 2>,
                         cudaFuncAttributeMaxDynamicSharedMemorySize, SMEM1);
    cudaFuncSetAttribute((const void*)sage_mma_kernel<2, 64, 2, 4>,
                         cudaFuncAttributeMaxDynamicSharedMemorySize, SMEM2);

    sage_mma_kernel<1, 128, 4, 2><<<N1 / 128, NTHREADS, SMEM1>>>(
        raw_features, W1, layer1_nodes, neigh0_idx, nullptr);
    sage_mma_kernel<2, 64, 2, 4><<<BATCH / 64, NTHREADS, SMEM2>>>(
        nullptr, W2, map_batch, neigh1_idx, out);
}

// round 12
// speedup vs baseline: 1.2121x; 1.2121x over previous
#include <cuda_runtime.h>
#include <cuda_bf16.h>
#include <cstdint>

#define D        128
#define N1       81920
#define BATCH    8192
#define KNB      10
#define NTHREADS 256
#define KPAD     136        // padded k-stride in bf16 elems
#define ROWB     (KPAD * 2) // 272 bytes per row

// ---------------- device-global scratch (allocation-free rule) ----------------
__device__ float g_h1[(size_t)N1 * D];                 // layer-1 embeddings

// ---------------- PTX helpers ----------------
__device__ __forceinline__ uint32_t smem_u32(const void* p) {
    uint32_t a;
    asm("{ .reg .u64 t; cvta.to.shared.u64 t, %1; cvt.u32.u64 %0, t; }"
        : "=r"(a) : "l"(p));
    return a;
}
#define LDSM4(r, addr)                                                       \
    asm volatile("ldmatrix.sync.aligned.m8n8.x4.shared.b16 {%0,%1,%2,%3}, [%4];" \
                 : "=r"((r)[0]), "=r"((r)[1]), "=r"((r)[2]), "=r"((r)[3])    \
                 : "r"(addr))
#define MMA16816(c, a, b0, b1)                                               \
    asm volatile("mma.sync.aligned.m16n8k16.row.col.f32.bf16.bf16.f32 "      \
                 "{%0,%1,%2,%3}, {%4,%5,%6,%7}, {%8,%9}, {%0,%1,%2,%3};"     \
                 : "+f"((c)[0]), "+f"((c)[1]), "+f"((c)[2]), "+f"((c)[3])    \
                 : "r"((a)[0]), "r"((a)[1]), "r"((a)[2]), "r"((a)[3]),       \
                   "r"(b0), "r"(b1))

__device__ __forceinline__ uint32_t pack_bf2(float a, float b) {
    __nv_bfloat16 ha = __float2bfloat16_rn(a), hb = __float2bfloat16_rn(b);
    return (uint32_t)__bfloat16_as_ushort(ha) |
           ((uint32_t)__bfloat16_as_ushort(hb) << 16);
}
// split float4 into bf16 hi + bf16 residual lo; 8-B store each
__device__ __forceinline__ void split_store(char* hi_p, char* lo_p, float4 v) {
    __nv_bfloat16 hx = __float2bfloat16_rn(v.x), hy = __float2bfloat16_rn(v.y);
    __nv_bfloat16 hz = __float2bfloat16_rn(v.z), hw = __float2bfloat16_rn(v.w);
    uint2 hv, lv;
    hv.x = (uint32_t)__bfloat16_as_ushort(hx) | ((uint32_t)__bfloat16_as_ushort(hy) << 16);
    hv.y = (uint32_t)__bfloat16_as_ushort(hz) | ((uint32_t)__bfloat16_as_ushort(hw) << 16);
    lv.x = pack_bf2(v.x - __bfloat162float(hx), v.y - __bfloat162float(hy));
    lv.y = pack_bf2(v.z - __bfloat162float(hz), v.w - __bfloat162float(hw));
    *(uint2*)hi_p = hv;
    *(uint2*)lo_p = lv;
}

// one K=128 phase of the split GEMM: acc += Ah*Bh + Al*Bh + Ah*Bl
template <int NQ>
__device__ __forceinline__ void mma_phase(uint32_t aH, uint32_t aL,
                                          uint32_t bH, uint32_t bL,
                                          int lane, float acc[2][2 * NQ][4]) {
    const uint32_t pa = (uint32_t)((lane & 15) * ROWB + (lane >> 4) * 16);
    const uint32_t pb = (uint32_t)(((lane & 7) + ((lane >> 4) << 3)) * ROWB +
                                   ((lane >> 3) & 1) * 16);
    #pragma unroll
    for (int ks = 0; ks < 8; ks++) {
        const uint32_t ko = ks * 32;
        uint32_t ah[2][4], al[2][4];
        #pragma unroll
        for (int mt = 0; mt < 2; mt++) {
            LDSM4(ah[mt], aH + pa + mt * 16 * ROWB + ko);
            LDSM4(al[mt], aL + pa + mt * 16 * ROWB + ko);
        }
        #pragma unroll
        for (int nq = 0; nq < NQ; nq++) {
            uint32_t bh[4], bl[4];
            LDSM4(bh, bH + pb + nq * 16 * ROWB + ko);
            LDSM4(bl, bL + pb + nq * 16 * ROWB + ko);
            #pragma unroll
            for (int mt = 0; mt < 2; mt++) {
                MMA16816(acc[mt][nq * 2 + 0], ah[mt], bh[0], bh[1]);
                MMA16816(acc[mt][nq * 2 + 1], ah[mt], bh[2], bh[3]);
                MMA16816(acc[mt][nq * 2 + 0], al[mt], bh[0], bh[1]);
                MMA16816(acc[mt][nq * 2 + 1], al[mt], bh[2], bh[3]);
                MMA16816(acc[mt][nq * 2 + 0], ah[mt], bl[0], bl[1]);
                MMA16816(acc[mt][nq * 2 + 1], ah[mt], bl[2], bl[3]);
            }
        }
    }
}

// ---------------- fused SAGE layer -------------------------------------------
// TM_ rows per block. Warp grid: WM_ x WN_ (=8 warps), warp tile 32 x (128/WN_).
template <int LAYER, int TM_, int WM_, int WN_>
__global__ __launch_bounds__(NTHREADS, 1)
void sage_mma_kernel(const float* __restrict__ feats_in,
                     const float* __restrict__ Wg,
                     const int*   __restrict__ self_idx,
                     const int*   __restrict__ neigh_idx,
                     float*       __restrict__ out_ext) {
    constexpr int NW  = 128 / WN_;          // cols per warp tile
    constexpr int NQ  = NW / 16;
    constexpr int RPW = TM_ / 8;            // gather rows per warp
    constexpr int ATILE = TM_ * ROWB;
    constexpr int OFF_A0H = 0;
    constexpr int OFF_A0L = ATILE;
    constexpr int OFF_A1H = 2 * ATILE;
    constexpr int OFF_A1L = 3 * ATILE;
    constexpr int OFF_BH  = 4 * ATILE;
    constexpr int OFF_BL  = 4 * ATILE + 128 * ROWB;

    extern __shared__ char smem[];
    const uint32_t sb = smem_u32(smem);
    const int t = threadIdx.x, lane = t & 31, wid = t >> 5;

    const float* feats = (LAYER == 1) ? feats_in : g_h1;
    float*       out   = (LAYER == 1) ? g_h1 : out_ext;

    // ---- stage B phase 0: coalesced read of W[:, 0:128], split hi/lo ----
    {
        #pragma unroll
        for (int it = 0; it < 16; it++) {
            const int row = wid + it * 8;
            float4 v = __ldg((const float4*)(Wg + row * 256) + lane);
            split_store(smem + OFF_BH + row * ROWB + lane * 8,
                        smem + OFF_BL + row * ROWB + lane * 8, v);
        }
    }

    // ---- gather: RPW rows/warp, R7-proven shape (no index hoisting) ----
    {
        #pragma unroll 2
        for (int rr = 0; rr < RPW; rr++) {
            const int r    = wid * RPW + rr;
            const int row  = blockIdx.x * TM_ + r;
            const int nsel = __ldg(&self_idx[row]);
            float4 s = __ldg((const float4*)&feats[(size_t)nsel * D] + lane);
            float4 a = make_float4(0.f, 0.f, 0.f, 0.f);
            #pragma unroll
            for (int k = 0; k < KNB; k++) {
                const int nk = __ldg(&neigh_idx[row * KNB + k]);
                float4 f = __ldg((const float4*)&feats[(size_t)nk * D] + lane);
                a.x += f.x; a.y += f.y; a.z += f.z; a.w += f.w;
            }
            const float inv = 1.0f / (float)KNB;
            a.x *= inv; a.y *= inv; a.z *= inv; a.w *= inv;
            const int so = r * ROWB + lane * 8;
            split_store(smem + OFF_A0H + so, smem + OFF_A0L + so, s);
            split_store(smem + OFF_A1H + so, smem + OFF_A1L + so, a);
        }
    }
    __syncthreads();

    // ---- warp tiling ----
    const int wm = wid % WM_, wn = wid / WM_;
    const uint32_t aoff = (uint32_t)(wm * 32 * ROWB);
    const uint32_t boff = (uint32_t)(wn * NW * ROWB);

    float acc[2][2 * NQ][4];
    #pragma unroll
    for (int mt = 0; mt < 2; mt++)
        #pragma unroll
        for (int nt = 0; nt < 2 * NQ; nt++)
            #pragma unroll
            for (int c = 0; c < 4; c++) acc[mt][nt][c] = 0.0f;

    // ---- phase 0: self features x W[:, 0:128] ----
    mma_phase<NQ>(sb + OFF_A0H + aoff, sb + OFF_A0L + aoff,
                  sb + OFF_BH + boff,  sb + OFF_BL + boff, lane, acc);

    // ---- restage B for phase 1 ----
    __syncthreads();
    {
        #pragma unroll
        for (int it = 0; it < 16; it++) {
            const int row = wid + it * 8;
            float4 v = __ldg((const float4*)(Wg + row * 256 + 128) + lane);
            split_store(smem + OFF_BH + row * ROWB + lane * 8,
                        smem + OFF_BL + row * ROWB + lane * 8, v);
        }
    }
    __syncthreads();

    // ---- phase 1: agg features x W[:, 128:256] ----
    mma_phase<NQ>(sb + OFF_A1H + aoff, sb + OFF_A1L + aoff,
                  sb + OFF_BH + boff,  sb + OFF_BL + boff, lane, acc);

    // ---- epilogue: ReLU + float2 stores ----
    const int rb = blockIdx.x * TM_ + wm * 32 + (lane >> 2);
    const int cb = wn * NW + (lane & 3) * 2;
    #pragma unroll
    for (int mt = 0; mt < 2; mt++)
        #pragma unroll
        for (int nt = 0; nt < 2 * NQ; nt++) {
            const int row = rb + mt * 16;
            const int col = cb + nt * 8;
            float2 v0 = make_float2(fmaxf(acc[mt][nt][0], 0.f),
                                    fmaxf(acc[mt][nt][1], 0.f));
            float2 v1 = make_float2(fmaxf(acc[mt][nt][2], 0.f),
                                    fmaxf(acc[mt][nt][3], 0.f));
            *(float2*)&out[(size_t)row * D + col]       = v0;
            *(float2*)&out[(size_t)(row + 8) * D + col] = v1;
        }
}

// ---------------- launch ----------------
extern "C" void kernel_launch(void* const* d_in, const int* in_sizes, int n_in,
                              void* d_out, int out_size) {
    const float* raw_features = (const float*)d_in[0];
    const float* W1           = (const float*)d_in[1];
    const float* W2           = (const float*)d_in[2];
    const int*   layer1_nodes = (const int*)d_in[3];
    const int*   neigh0_idx   = (const int*)d_in[4];
    const int*   map_batch    = (const int*)d_in[5];
    const int*   neigh1_idx   = (const int*)d_in[6];
    float*       out          = (float*)d_out;

    // layer 1: TM=128, warps 4m x 2n (tile 32x64)
    constexpr int SMEM1 = 4 * 128 * ROWB + 2 * 128 * ROWB;   // 208896
    // layer 2: TM=64,  warps 2m x 4n (tile 32x32)
    constexpr int SMEM2 = 4 * 64 * ROWB + 2 * 128 * ROWB;    // 139264

    cudaFuncSetAttribute((const void*)sage_mma_kernel<1, 128, 4, 2>,
                         cudaFuncAttributeMaxDynamicSharedMemorySize, SMEM1);
    cudaFuncSetAttribute((const void*)sage_mma_kernel<2, 64, 2, 4>,
                         cudaFuncAttributeMaxDynamicSharedMemorySize, SMEM2);

    sage_mma_kernel<1, 128, 4, 2><<<N1 / 128, NTHREADS, SMEM1>>>(
        raw_features, W1, layer1_nodes, neigh0_idx, nullptr);
    sage_mma_kernel<2, 64, 2, 4><<<BATCH / 64, NTHREADS, SMEM2>>>(
        nullptr, W2, map_batch, neigh1_idx, out);
}

// round 13
// speedup vs baseline: 1.6490x; 1.3604x over previous
#include <cuda_runtime.h>
#include <cuda_fp16.h>
#include <cstdint>

#define D        128
#define N1       81920
#define BATCH    8192
#define KNB      10
#define NTHREADS 256
#define KPAD     136        // padded k-stride in fp16 elems
#define ROWB     (KPAD * 2) // 272 bytes per row

// ---------------- device-global scratch (allocation-free rule) ----------------
__device__ float g_h1[(size_t)N1 * D];                 // layer-1 embeddings

// ---------------- PTX helpers ----------------
__device__ __forceinline__ uint32_t smem_u32(const void* p) {
    uint32_t a;
    asm("{ .reg .u64 t; cvta.to.shared.u64 t, %1; cvt.u32.u64 %0, t; }"
        : "=r"(a) : "l"(p));
    return a;
}
#define LDSM4(r, addr)                                                       \
    asm volatile("ldmatrix.sync.aligned.m8n8.x4.shared.b16 {%0,%1,%2,%3}, [%4];" \
                 : "=r"((r)[0]), "=r"((r)[1]), "=r"((r)[2]), "=r"((r)[3])    \
                 : "r"(addr))
#define MMAF16(c, a, b0, b1)                                                 \
    asm volatile("mma.sync.aligned.m16n8k16.row.col.f32.f16.f16.f32 "        \
                 "{%0,%1,%2,%3}, {%4,%5,%6,%7}, {%8,%9}, {%0,%1,%2,%3};"     \
                 : "+f"((c)[0]), "+f"((c)[1]), "+f"((c)[2]), "+f"((c)[3])    \
                 : "r"((a)[0]), "r"((a)[1]), "r"((a)[2]), "r"((a)[3]),       \
                   "r"(b0), "r"(b1))

__device__ __forceinline__ uint32_t pack_h2(float a, float b) {
    __half2 h = __floats2half2_rn(a, b);
    return *(uint32_t*)&h;
}
// split float4 into fp16 hi + fp16 residual lo; 8-B store each
__device__ __forceinline__ void split_store_f16(char* hi_p, char* lo_p, float4 v) {
    __half hx = __float2half_rn(v.x), hy = __float2half_rn(v.y);
    __half hz = __float2half_rn(v.z), hw = __float2half_rn(v.w);
    uint2 hv, lv;
    hv.x = (uint32_t)*(unsigned short*)&hx | ((uint32_t)*(unsigned short*)&hy << 16);
    hv.y = (uint32_t)*(unsigned short*)&hz | ((uint32_t)*(unsigned short*)&hw << 16);
    lv.x = pack_h2(v.x - __half2float(hx), v.y - __half2float(hy));
    lv.y = pack_h2(v.z - __half2float(hz), v.w - __half2float(hw));
    *(uint2*)hi_p = hv;
    *(uint2*)lo_p = lv;
}

// one K=128 phase, 2-product fp16 split-A GEMM: acc += Ah*B + Al*B
template <int NQ>
__device__ __forceinline__ void mma_phase(uint32_t aH, uint32_t aL, uint32_t bB,
                                          int lane, float acc[2][2 * NQ][4]) {
    const uint32_t pa = (uint32_t)((lane & 15) * ROWB + (lane >> 4) * 16);
    const uint32_t pb = (uint32_t)(((lane & 7) + ((lane >> 4) << 3)) * ROWB +
                                   ((lane >> 3) & 1) * 16);
    #pragma unroll
    for (int ks = 0; ks < 8; ks++) {
        const uint32_t ko = ks * 32;
        uint32_t ah[2][4], al[2][4];
        #pragma unroll
        for (int mt = 0; mt < 2; mt++) {
            LDSM4(ah[mt], aH + pa + mt * 16 * ROWB + ko);
            LDSM4(al[mt], aL + pa + mt * 16 * ROWB + ko);
        }
        #pragma unroll
        for (int nq = 0; nq < NQ; nq++) {
            uint32_t b[4];
            LDSM4(b, bB + pb + nq * 16 * ROWB + ko);
            #pragma unroll
            for (int mt = 0; mt < 2; mt++) {
                MMAF16(acc[mt][nq * 2 + 0], ah[mt], b[0], b[1]);
                MMAF16(acc[mt][nq * 2 + 1], ah[mt], b[2], b[3]);
                MMAF16(acc[mt][nq * 2 + 0], al[mt], b[0], b[1]);
                MMAF16(acc[mt][nq * 2 + 1], al[mt], b[2], b[3]);
            }
        }
    }
}

// ---------------- fused SAGE layer, TM=64, 2 CTAs/SM --------------------------
// 8 warps: 2(m) x 4(n), warp tile 32 x 32. Phases: self x W[:,0:128], agg x W[:,128:256].
template <int LAYER>
__global__ __launch_bounds__(NTHREADS, 2)
void sage_mma_kernel(const float* __restrict__ feats_in,
                     const float* __restrict__ Wg,
                     const int*   __restrict__ self_idx,
                     const int*   __restrict__ neigh_idx,
                     float*       __restrict__ out_ext) {
    constexpr int TM_ = 64, WM_ = 2, NQ = 2;
    constexpr int NW  = 32;                 // cols per warp tile
    constexpr int RPW = 8;                  // gather rows per warp
    constexpr int ATILE = TM_ * ROWB;       // 17408
    constexpr int OFF_A0H = 0;
    constexpr int OFF_A0L = ATILE;
    constexpr int OFF_A1H = 2 * ATILE;
    constexpr int OFF_A1L = 3 * ATILE;
    constexpr int OFF_B   = 4 * ATILE;      // fp16 [128 n][KPAD] = 34816

    extern __shared__ char smem[];
    const uint32_t sb = smem_u32(smem);
    const int t = threadIdx.x, lane = t & 31, wid = t >> 5;

    const float* feats = (LAYER == 1) ? feats_in : g_h1;
    float*       out   = (LAYER == 1) ? g_h1 : out_ext;

    // ---- stage B phase 0: W[:, 0:128] -> fp16 ----
    {
        #pragma unroll
        for (int it = 0; it < 16; it++) {
            const int row = wid + it * 8;
            float4 v = __ldg((const float4*)(Wg + row * 256) + lane);
            uint2 hv;
            hv.x = pack_h2(v.x, v.y);
            hv.y = pack_h2(v.z, v.w);
            *(uint2*)(smem + OFF_B + row * ROWB + lane * 8) = hv;
        }
    }

    // ---- gather: 8 rows/warp; self -> A0 (hi/lo), mean-agg -> A1 (hi/lo) ----
    {
        #pragma unroll 2
        for (int rr = 0; rr < RPW; rr++) {
            const int r    = wid * RPW + rr;
            const int row  = blockIdx.x * TM_ + r;
            const int nsel = __ldg(&self_idx[row]);
            float4 s = __ldg((const float4*)&feats[(size_t)nsel * D] + lane);
            float4 a = make_float4(0.f, 0.f, 0.f, 0.f);
            #pragma unroll
            for (int k = 0; k < KNB; k++) {
                const int nk = __ldg(&neigh_idx[row * KNB + k]);
                float4 f = __ldg((const float4*)&feats[(size_t)nk * D] + lane);
                a.x += f.x; a.y += f.y; a.z += f.z; a.w += f.w;
            }
            const float inv = 1.0f / (float)KNB;
            a.x *= inv; a.y *= inv; a.z *= inv; a.w *= inv;
            const int so = r * ROWB + lane * 8;
            split_store_f16(smem + OFF_A0H + so, smem + OFF_A0L + so, s);
            split_store_f16(smem + OFF_A1H + so, smem + OFF_A1L + so, a);
        }
    }
    __syncthreads();

    // ---- warp tiling: 2(m) x 4(n) ----
    const int wm = wid % WM_, wn = wid / WM_;
    const uint32_t aoff = (uint32_t)(wm * 32 * ROWB);
    const uint32_t boff = (uint32_t)(wn * NW * ROWB);

    float acc[2][2 * NQ][4];
    #pragma unroll
    for (int mt = 0; mt < 2; mt++)
        #pragma unroll
        for (int nt = 0; nt < 2 * NQ; nt++)
            #pragma unroll
            for (int c = 0; c < 4; c++) acc[mt][nt][c] = 0.0f;

    // ---- phase 0: self x W[:, 0:128] ----
    mma_phase<NQ>(sb + OFF_A0H + aoff, sb + OFF_A0L + aoff,
                  sb + OFF_B + boff, lane, acc);

    // ---- restage B for phase 1: W[:, 128:256] ----
    __syncthreads();
    {
        #pragma unroll
        for (int it = 0; it < 16; it++) {
            const int row = wid + it * 8;
            float4 v = __ldg((const float4*)(Wg + row * 256 + 128) + lane);
            uint2 hv;
            hv.x = pack_h2(v.x, v.y);
            hv.y = pack_h2(v.z, v.w);
            *(uint2*)(smem + OFF_B + row * ROWB + lane * 8) = hv;
        }
    }
    __syncthreads();

    // ---- phase 1: agg x W[:, 128:256] ----
    mma_phase<NQ>(sb + OFF_A1H + aoff, sb + OFF_A1L + aoff,
                  sb + OFF_B + boff, lane, acc);

    // ---- epilogue: ReLU + float2 stores ----
    const int rb = blockIdx.x * TM_ + wm * 32 + (lane >> 2);
    const int cb = wn * NW + (lane & 3) * 2;
    #pragma unroll
    for (int mt = 0; mt < 2; mt++)
        #pragma unroll
        for (int nt = 0; nt < 2 * NQ; nt++) {
            const int row = rb + mt * 16;
            const int col = cb + nt * 8;
            float2 v0 = make_float2(fmaxf(acc[mt][nt][0], 0.f),
                                    fmaxf(acc[mt][nt][1], 0.f));
            float2 v1 = make_float2(fmaxf(acc[mt][nt][2], 0.f),
                                    fmaxf(acc[mt][nt][3], 0.f));
            *(float2*)&out[(size_t)row * D + col]       = v0;
            *(float2*)&out[(size_t)(row + 8) * D + col] = v1;
        }
}

// ---------------- launch ----------------
extern "C" void kernel_launch(void* const* d_in, const int* in_sizes, int n_in,
                              void* d_out, int out_size) {
    const float* raw_features = (const float*)d_in[0];
    const float* W1           = (const float*)d_in[1];
    const float* W2           = (const float*)d_in[2];
    const int*   layer1_nodes = (const int*)d_in[3];
    const int*   neigh0_idx   = (const int*)d_in[4];
    const int*   map_batch    = (const int*)d_in[5];
    const int*   neigh1_idx   = (const int*)d_in[6];
    float*       out          = (float*)d_out;

    constexpr int SMEM = 4 * 64 * ROWB + 128 * ROWB;   // 104448 B (~102 KB)

    cudaFuncSetAttribute((const void*)sage_mma_kernel<1>,
                         cudaFuncAttributeMaxDynamicSharedMemorySize, SMEM);
    cudaFuncSetAttribute((const void*)sage_mma_kernel<2>,
                         cudaFuncAttributeMaxDynamicSharedMemorySize, SMEM);

    sage_mma_kernel<1><<<N1 / 64, NTHREADS, SMEM>>>(
        raw_features, W1, layer1_nodes, neigh0_idx, nullptr);
    sage_mma_kernel<2><<<BATCH / 64, NTHREADS, SMEM>>>(
        nullptr, W2, map_batch, neigh1_idx, out);
}